// round 2
// baseline (speedup 1.0000x reference)
#include <cuda_runtime.h>
#include <cuda_bf16.h>

#define N_PTS 16384
#define KNN   16

// Scratch (no cudaMalloc allowed)
__device__ int   g_nbr[N_PTS * KNN];
__device__ float g_h0[N_PTS * 6];

// ---------------------------------------------------------------------------
// kNN: one thread per query point. Scan all points in shared tiles, maintain
// a sorted top-16 (ascending d2) in local arrays. d2 computed with the same
// algebra as the reference (sq_i + sq_j - 2*dot) so self-distance is exactly 0.
// ---------------------------------------------------------------------------
__global__ void __launch_bounds__(128) knn_kernel(const float* __restrict__ pos,
                                                  int* __restrict__ nbr)
{
    const int q = blockIdx.x * 128 + threadIdx.x;
    const float px = pos[3 * q], py = pos[3 * q + 1], pz = pos[3 * q + 2];
    const float sq = fmaf(px, px, fmaf(py, py, pz * pz));

    __shared__ float4 tile[128];

    float bestd[KNN];
    int   besti[KNN];
#pragma unroll
    for (int r = 0; r < KNN; r++) { bestd[r] = 3.4e38f; besti[r] = -1; }
    float thr = 3.4e38f;

    for (int t0 = 0; t0 < N_PTS; t0 += 128) {
        const int j = t0 + threadIdx.x;
        const float x = pos[3 * j], y = pos[3 * j + 1], z = pos[3 * j + 2];
        __syncthreads();
        tile[threadIdx.x] = make_float4(x, y, z, fmaf(x, x, fmaf(y, y, z * z)));
        __syncthreads();
#pragma unroll 8
        for (int jj = 0; jj < 128; jj++) {
            const float4 c = tile[jj];
            const float dot = fmaf(px, c.x, fmaf(py, c.y, pz * c.z));
            const float d2  = fmaf(-2.0f, dot, sq + c.w);
            if (d2 < thr) {
                const int idx = t0 + jj;
                int p = KNN - 1;
#pragma unroll 1
                while (p > 0 && bestd[p - 1] > d2) {
                    bestd[p] = bestd[p - 1];
                    besti[p] = besti[p - 1];
                    p--;
                }
                bestd[p] = d2;
                besti[p] = idx;
                thr = bestd[KNN - 1];
            }
        }
    }
#pragma unroll
    for (int r = 0; r < KNN; r++) nbr[q * KNN + r] = besti[r];
}

// ---------------------------------------------------------------------------
// concat(pos, normal) -> h0[N,6]
// ---------------------------------------------------------------------------
__global__ void concat_kernel(const float* __restrict__ pos,
                              const float* __restrict__ normal,
                              float* __restrict__ h0)
{
    const int i = blockIdx.x * 256 + threadIdx.x;
    if (i < N_PTS) {
#pragma unroll
        for (int c = 0; c < 3; c++) {
            h0[i * 6 + c]     = pos[i * 3 + c];
            h0[i * 6 + 3 + c] = normal[i * 3 + c];
        }
    }
}

// ---------------------------------------------------------------------------
// Fused PointNetConv layer:
//   per edge: m = [x_j, pos_j - pos_i];  h = relu(GN(m@Wa + ba));  o = h@Wb + bb
//   per node: out = relu(max over 16 edges of o)
// Block = 256 threads = 16 nodes x 16 edges (one thread per edge).
// h kept fully in registers (statically indexed). Weights in shared memory.
// ---------------------------------------------------------------------------
template <int CIN_X, int COUT1, int COUT2, int GROUPS>
__global__ void __launch_bounds__(256) conv_kernel(
    const float* __restrict__ x, const float* __restrict__ pos,
    const int* __restrict__ nbr,
    const float* __restrict__ Wa, const float* __restrict__ ba,
    const float* __restrict__ gmm, const float* __restrict__ bet,
    const float* __restrict__ Wb, const float* __restrict__ bb,
    float* __restrict__ out)
{
    constexpr int CIN = CIN_X + 3;
    constexpr int GS  = COUT1 / GROUPS;

    extern __shared__ float sm[];
    float* sWa = sm;                       // CIN*COUT1
    float* sba = sWa + CIN * COUT1;        // COUT1
    float* sg  = sba + COUT1;              // COUT1
    float* sbe = sg + COUT1;               // COUT1
    float* sWb = sbe + COUT1;              // COUT1*COUT2 (16B aligned)
    float* sbb = sWb + COUT1 * COUT2;      // COUT2

    const int tid = threadIdx.x;
    for (int i = tid; i < CIN * COUT1; i += 256) sWa[i] = Wa[i];
    for (int i = tid; i < COUT1 * COUT2; i += 256) sWb[i] = Wb[i];
    if (tid < COUT1) { sba[tid] = ba[tid]; sg[tid] = gmm[tid]; sbe[tid] = bet[tid]; }
    if (tid < COUT2) sbb[tid] = bb[tid];
    __syncthreads();

    const int node = (blockIdx.x << 4) + (tid >> 4);
    const int e    = tid & 15;
    const int j    = nbr[(node << 4) + e];

    const float rx = pos[3 * j]     - pos[3 * node];
    const float ry = pos[3 * j + 1] - pos[3 * node + 1];
    const float rz = pos[3 * j + 2] - pos[3 * node + 2];

    float h[COUT1];
#pragma unroll
    for (int c = 0; c < COUT1; c++) h[c] = sba[c];

    // ---- Linear 1: x_j part ----
    if constexpr (CIN_X % 4 == 0) {
        const float4* xj4 = (const float4*)(x + (long)j * CIN_X);
        float4 cur = __ldg(xj4);
#pragma unroll 1
        for (int i4 = 0; i4 < CIN_X / 4; i4++) {
            const float4 nxt = (i4 + 1 < CIN_X / 4) ? __ldg(xj4 + i4 + 1) : cur;
            const float mi[4] = {cur.x, cur.y, cur.z, cur.w};
#pragma unroll
            for (int r = 0; r < 4; r++) {
                const float m = mi[r];
                const float4* w4 = (const float4*)(sWa + (i4 * 4 + r) * COUT1);
#pragma unroll
                for (int c4 = 0; c4 < COUT1 / 4; c4++) {
                    const float4 w = w4[c4];
                    h[4 * c4 + 0] = fmaf(m, w.x, h[4 * c4 + 0]);
                    h[4 * c4 + 1] = fmaf(m, w.y, h[4 * c4 + 1]);
                    h[4 * c4 + 2] = fmaf(m, w.z, h[4 * c4 + 2]);
                    h[4 * c4 + 3] = fmaf(m, w.w, h[4 * c4 + 3]);
                }
            }
            cur = nxt;
        }
    } else {
        const float* xj = x + (long)j * CIN_X;
        float mi = __ldg(xj);
#pragma unroll 1
        for (int i = 0; i < CIN_X; i++) {
            const float nxt = (i + 1 < CIN_X) ? __ldg(xj + i + 1) : mi;
            const float4* w4 = (const float4*)(sWa + i * COUT1);
#pragma unroll
            for (int c4 = 0; c4 < COUT1 / 4; c4++) {
                const float4 w = w4[c4];
                h[4 * c4 + 0] = fmaf(mi, w.x, h[4 * c4 + 0]);
                h[4 * c4 + 1] = fmaf(mi, w.y, h[4 * c4 + 1]);
                h[4 * c4 + 2] = fmaf(mi, w.z, h[4 * c4 + 2]);
                h[4 * c4 + 3] = fmaf(mi, w.w, h[4 * c4 + 3]);
            }
            mi = nxt;
        }
    }

    // ---- Linear 1: rel part ----
    {
        const float m3[3] = {rx, ry, rz};
#pragma unroll
        for (int r = 0; r < 3; r++) {
            const float m = m3[r];
            const float4* w4 = (const float4*)(sWa + (CIN_X + r) * COUT1);
#pragma unroll
            for (int c4 = 0; c4 < COUT1 / 4; c4++) {
                const float4 w = w4[c4];
                h[4 * c4 + 0] = fmaf(m, w.x, h[4 * c4 + 0]);
                h[4 * c4 + 1] = fmaf(m, w.y, h[4 * c4 + 1]);
                h[4 * c4 + 2] = fmaf(m, w.z, h[4 * c4 + 2]);
                h[4 * c4 + 3] = fmaf(m, w.w, h[4 * c4 + 3]);
            }
        }
    }

    // ---- GroupNorm + ReLU (per edge, groups of GS channels) ----
#pragma unroll
    for (int g = 0; g < GROUPS; g++) {
        float s = 0.f, s2 = 0.f;
#pragma unroll
        for (int u = 0; u < GS; u++) {
            const float v = h[g * GS + u];
            s += v;
            s2 = fmaf(v, v, s2);
        }
        const float mu  = s * (1.0f / GS);
        const float var = fmaf(-mu, mu, s2 * (1.0f / GS));
        const float rs  = rsqrtf(var + 1e-5f);
#pragma unroll
        for (int u = 0; u < GS; u++) {
            const int c = g * GS + u;
            float v = (h[c] - mu) * rs;
            v = fmaf(v, sg[c], sbe[c]);
            h[c] = fmaxf(v, 0.f);
        }
    }

    // ---- Linear 2 + max over 16 edges + ReLU + store ----
    float* outn = out + (long)node * COUT2;
#pragma unroll 1
    for (int c2 = 0; c2 < COUT2; c2 += 4) {
        float a0 = sbb[c2], a1 = sbb[c2 + 1], a2 = sbb[c2 + 2], a3 = sbb[c2 + 3];
        const float4* wb4 = (const float4*)(sWb + c2);
#pragma unroll
        for (int c = 0; c < COUT1; c++) {
            const float4 w = wb4[c * (COUT2 / 4)];
            a0 = fmaf(h[c], w.x, a0);
            a1 = fmaf(h[c], w.y, a1);
            a2 = fmaf(h[c], w.z, a2);
            a3 = fmaf(h[c], w.w, a3);
        }
#pragma unroll
        for (int off = 8; off >= 1; off >>= 1) {
            a0 = fmaxf(a0, __shfl_xor_sync(0xffffffffu, a0, off));
            a1 = fmaxf(a1, __shfl_xor_sync(0xffffffffu, a1, off));
            a2 = fmaxf(a2, __shfl_xor_sync(0xffffffffu, a2, off));
            a3 = fmaxf(a3, __shfl_xor_sync(0xffffffffu, a3, off));
        }
        if (e == 0) {
            outn[c2]     = fmaxf(a0, 0.f);
            outn[c2 + 1] = fmaxf(a1, 0.f);
            outn[c2 + 2] = fmaxf(a2, 0.f);
            outn[c2 + 3] = fmaxf(a3, 0.f);
        }
    }
}

// ---------------------------------------------------------------------------
extern "C" void kernel_launch(void* const* d_in, const int* in_sizes, int n_in,
                              void* d_out, int out_size)
{
    const float* pos    = (const float*)d_in[0];
    const float* normal = (const float*)d_in[1];
    const float* W1a = (const float*)d_in[2];
    const float* b1a = (const float*)d_in[3];
    const float* g1  = (const float*)d_in[4];
    const float* be1 = (const float*)d_in[5];
    const float* W1b = (const float*)d_in[6];
    const float* b1b = (const float*)d_in[7];
    const float* W2a = (const float*)d_in[8];
    const float* b2a = (const float*)d_in[9];
    const float* g2  = (const float*)d_in[10];
    const float* be2 = (const float*)d_in[11];
    const float* W2b = (const float*)d_in[12];
    const float* b2b = (const float*)d_in[13];
    const float* W3a = (const float*)d_in[14];
    const float* b3a = (const float*)d_in[15];
    const float* g3  = (const float*)d_in[16];
    const float* be3 = (const float*)d_in[17];
    const float* W3b = (const float*)d_in[18];
    const float* b3b = (const float*)d_in[19];

    float* out = (float*)d_out;
    float* h1 = out;                       // [N,64]
    float* h2 = out + (size_t)N_PTS * 64;  // [N,64]
    float* h3 = out + (size_t)N_PTS * 128; // [N,128]

    void* nbr_p = nullptr;
    void* h0_p  = nullptr;
    cudaGetSymbolAddress(&nbr_p, g_nbr);
    cudaGetSymbolAddress(&h0_p, g_h0);
    int*   nbr = (int*)nbr_p;
    float* h0  = (float*)h0_p;

    // dynamic smem sizes (floats): CIN*COUT1 + 3*COUT1 + COUT1*COUT2 + COUT2
    const int sm1 = (9 * 64 + 3 * 64 + 64 * 64 + 64) * 4;        // 19712 B
    const int sm2 = (67 * 64 + 3 * 64 + 64 * 64 + 64) * 4;       // 34560 B
    const int sm3 = (67 * 128 + 3 * 128 + 128 * 128 + 128) * 4;  // 101888 B

    cudaFuncSetAttribute(conv_kernel<6, 64, 64, 8>,
                         cudaFuncAttributeMaxDynamicSharedMemorySize, sm1);
    cudaFuncSetAttribute(conv_kernel<64, 64, 64, 8>,
                         cudaFuncAttributeMaxDynamicSharedMemorySize, sm2);
    cudaFuncSetAttribute(conv_kernel<64, 128, 128, 16>,
                         cudaFuncAttributeMaxDynamicSharedMemorySize, sm3);

    knn_kernel<<<N_PTS / 128, 128>>>(pos, nbr);
    concat_kernel<<<N_PTS / 256, 256>>>(pos, normal, h0);

    conv_kernel<6, 64, 64, 8><<<N_PTS / 16, 256, sm1>>>(
        h0, pos, nbr, W1a, b1a, g1, be1, W1b, b1b, h1);
    conv_kernel<64, 64, 64, 8><<<N_PTS / 16, 256, sm2>>>(
        h1, pos, nbr, W2a, b2a, g2, be2, W2b, b2b, h2);
    conv_kernel<64, 128, 128, 16><<<N_PTS / 16, 256, sm3>>>(
        h2, pos, nbr, W3a, b3a, g3, be3, W3b, b3b, h3);
}

// round 4
// speedup vs baseline: 2.6452x; 2.6452x over previous
#include <cuda_runtime.h>
#include <cuda_bf16.h>

#define N_PTS 16384
#define KNN   16

// Scratch (no cudaMalloc allowed)
__device__ int    g_nbr[N_PTS * KNN];
__device__ float  g_h0[N_PTS * 6];
__device__ float4 g_pos4[N_PTS];

// ---------------- packed f32x2 helpers (Blackwell FFMA2 path) ----------------
__device__ __forceinline__ unsigned long long pk2(float lo, float hi) {
    unsigned long long r;
    asm("mov.b64 %0, {%1, %2};" : "=l"(r) : "f"(lo), "f"(hi));
    return r;
}
__device__ __forceinline__ void upk2(unsigned long long v, float& lo, float& hi) {
    asm("mov.b64 {%0, %1}, %2;" : "=f"(lo), "=f"(hi) : "l"(v));
}
__device__ __forceinline__ void fma2(unsigned long long& d, unsigned long long a,
                                     unsigned long long b) {
    asm("fma.rn.f32x2 %0, %1, %2, %0;" : "+l"(d) : "l"(a), "l"(b));
}

// ---------------------------------------------------------------------------
// prep: pos -> float4 (x,y,z,|p|^2)
// ---------------------------------------------------------------------------
__global__ void prep_kernel(const float* __restrict__ pos, float4* __restrict__ p4)
{
    const int i = blockIdx.x * 256 + threadIdx.x;
    if (i < N_PTS) {
        const float x = pos[3 * i], y = pos[3 * i + 1], z = pos[3 * i + 2];
        p4[i] = make_float4(x, y, z, fmaf(x, x, fmaf(y, y, z * z)));
    }
}

// ---------------------------------------------------------------------------
// kNN: 1 thread per query. Branch-free statically-indexed insertion network —
// top-16 lives entirely in registers (no local memory, no divergent loops).
// d2 = sq_i + sq_j - 2*dot (same algebra as reference; self-distance exactly 0).
// ---------------------------------------------------------------------------
__global__ void __launch_bounds__(64) knn_kernel(const float4* __restrict__ p4,
                                                 int* __restrict__ nbr)
{
    const int tid = threadIdx.x;
    const int q   = blockIdx.x * 64 + tid;
    const float4 me = p4[q];
    const float px = me.x, py = me.y, pz = me.z, sq = me.w;

    __shared__ float4 tile[256];

    float bestd[KNN];
    int   besti[KNN];
#pragma unroll
    for (int r = 0; r < KNN; r++) { bestd[r] = 3.4e38f; besti[r] = 0; }
    float thr = 3.4e38f;

    for (int t0 = 0; t0 < N_PTS; t0 += 256) {
        __syncthreads();
#pragma unroll
        for (int u = 0; u < 4; u++) tile[tid + 64 * u] = p4[t0 + tid + 64 * u];
        __syncthreads();
#pragma unroll 4
        for (int jj = 0; jj < 256; jj++) {
            const float4 c = tile[jj];
            const float dot = fmaf(px, c.x, fmaf(py, c.y, pz * c.z));
            const float d2  = fmaf(-2.0f, dot, sq + c.w);
            if (d2 < thr) {
                const int idx = t0 + jj;
#pragma unroll
                for (int r = KNN - 1; r >= 1; r--) {
                    const bool keep  = bestd[r] <= d2;       // stable: ties keep old
                    const bool shift = bestd[r - 1] > d2;    // strict
                    bestd[r] = keep ? bestd[r] : (shift ? bestd[r - 1] : d2);
                    besti[r] = keep ? besti[r] : (shift ? besti[r - 1] : idx);
                }
                {
                    const bool keep = bestd[0] <= d2;
                    bestd[0] = keep ? bestd[0] : d2;
                    besti[0] = keep ? besti[0] : idx;
                }
                thr = bestd[KNN - 1];
            }
        }
    }
#pragma unroll
    for (int r = 0; r < KNN; r++) nbr[q * KNN + r] = besti[r];
}

// ---------------------------------------------------------------------------
// concat(pos, normal) -> h0[N,6]
// ---------------------------------------------------------------------------
__global__ void concat_kernel(const float* __restrict__ pos,
                              const float* __restrict__ normal,
                              float* __restrict__ h0)
{
    const int i = blockIdx.x * 256 + threadIdx.x;
    if (i < N_PTS) {
#pragma unroll
        for (int c = 0; c < 3; c++) {
            h0[i * 6 + c]     = pos[i * 3 + c];
            h0[i * 6 + 3 + c] = normal[i * 3 + c];
        }
    }
}

// ---------------------------------------------------------------------------
// Fused PointNetConv layer with packed f32x2 math.
// Block = 256 threads = 16 nodes x 16 edges (1 thread per edge).
// Hidden vector kept as packed pairs in registers; weights in shared memory.
// ---------------------------------------------------------------------------
template <int CIN_X, int COUT1, int COUT2, int GROUPS>
__global__ void __launch_bounds__(256) conv_kernel(
    const float* __restrict__ x, const float* __restrict__ pos,
    const int* __restrict__ nbr,
    const float* __restrict__ Wa, const float* __restrict__ ba,
    const float* __restrict__ gmm, const float* __restrict__ bet,
    const float* __restrict__ Wb, const float* __restrict__ bb,
    float* __restrict__ out)
{
    constexpr int CIN = CIN_X + 3;
    constexpr int GS  = COUT1 / GROUPS;
    constexpr int NP  = COUT1 / 2;   // number of packed hidden pairs

    extern __shared__ float sm[];
    float* sWa = sm;                       // CIN*COUT1
    float* sba = sWa + CIN * COUT1;        // COUT1
    float* sg  = sba + COUT1;              // COUT1
    float* sbe = sg + COUT1;               // COUT1
    float* sWb = sbe + COUT1;              // COUT1*COUT2 (16B aligned)
    float* sbb = sWb + COUT1 * COUT2;      // COUT2

    const int tid = threadIdx.x;
    for (int i = tid; i < CIN * COUT1; i += 256) sWa[i] = Wa[i];
    for (int i = tid; i < COUT1 * COUT2; i += 256) sWb[i] = Wb[i];
    if (tid < COUT1) { sba[tid] = ba[tid]; sg[tid] = gmm[tid]; sbe[tid] = bet[tid]; }
    if (tid < COUT2) sbb[tid] = bb[tid];
    __syncthreads();

    const int node = (blockIdx.x << 4) + (tid >> 4);
    const int e    = tid & 15;
    const int j    = nbr[(node << 4) + e];

    const float rx = pos[3 * j]     - pos[3 * node];
    const float ry = pos[3 * j + 1] - pos[3 * node + 1];
    const float rz = pos[3 * j + 2] - pos[3 * node + 2];

    unsigned long long hacc[NP];
#pragma unroll
    for (int p = 0; p < NP; p++) hacc[p] = pk2(sba[2 * p], sba[2 * p + 1]);

    // ---- Linear 1: x_j part (packed pairs; weights as ulonglong2 = LDS.128) ----
    if constexpr (CIN_X % 4 == 0) {
        const float4* xj4 = (const float4*)(x + (long)j * CIN_X);
        float4 cur = __ldg(xj4);
#pragma unroll 1
        for (int i4 = 0; i4 < CIN_X / 4; i4++) {
            const float4 nxt = (i4 + 1 < CIN_X / 4) ? __ldg(xj4 + i4 + 1) : cur;
            const float mi[4] = {cur.x, cur.y, cur.z, cur.w};
#pragma unroll
            for (int r = 0; r < 4; r++) {
                const unsigned long long md = pk2(mi[r], mi[r]);
                const ulonglong2* w2 = (const ulonglong2*)(sWa + (i4 * 4 + r) * COUT1);
#pragma unroll
                for (int c4 = 0; c4 < COUT1 / 4; c4++) {
                    const ulonglong2 w = w2[c4];
                    fma2(hacc[2 * c4 + 0], md, w.x);
                    fma2(hacc[2 * c4 + 1], md, w.y);
                }
            }
            cur = nxt;
        }
    } else {
        const float* xj = x + (long)j * CIN_X;
        float mi = __ldg(xj);
#pragma unroll 1
        for (int i = 0; i < CIN_X; i++) {
            const float nxt = (i + 1 < CIN_X) ? __ldg(xj + i + 1) : mi;
            const unsigned long long md = pk2(mi, mi);
            const ulonglong2* w2 = (const ulonglong2*)(sWa + i * COUT1);
#pragma unroll
            for (int c4 = 0; c4 < COUT1 / 4; c4++) {
                const ulonglong2 w = w2[c4];
                fma2(hacc[2 * c4 + 0], md, w.x);
                fma2(hacc[2 * c4 + 1], md, w.y);
            }
            mi = nxt;
        }
    }

    // ---- Linear 1: rel part ----
    {
        const float m3[3] = {rx, ry, rz};
#pragma unroll
        for (int r = 0; r < 3; r++) {
            const unsigned long long md = pk2(m3[r], m3[r]);
            const ulonglong2* w2 = (const ulonglong2*)(sWa + (CIN_X + r) * COUT1);
#pragma unroll
            for (int c4 = 0; c4 < COUT1 / 4; c4++) {
                const ulonglong2 w = w2[c4];
                fma2(hacc[2 * c4 + 0], md, w.x);
                fma2(hacc[2 * c4 + 1], md, w.y);
            }
        }
    }

    // ---- GroupNorm + ReLU (per edge, groups of GS contiguous channels) ----
#pragma unroll
    for (int g = 0; g < GROUPS; g++) {
        float v[GS];
#pragma unroll
        for (int u2 = 0; u2 < GS / 2; u2++)
            upk2(hacc[g * (GS / 2) + u2], v[2 * u2], v[2 * u2 + 1]);
        float s = 0.f, s2 = 0.f;
#pragma unroll
        for (int u = 0; u < GS; u++) { s += v[u]; s2 = fmaf(v[u], v[u], s2); }
        const float mu  = s * (1.0f / GS);
        const float var = fmaf(-mu, mu, s2 * (1.0f / GS));
        const float rs  = rsqrtf(var + 1e-5f);
#pragma unroll
        for (int u = 0; u < GS; u++) {
            const int c = g * GS + u;
            float t = (v[u] - mu) * rs;
            t = fmaf(t, sg[c], sbe[c]);
            v[u] = fmaxf(t, 0.f);
        }
#pragma unroll
        for (int u2 = 0; u2 < GS / 2; u2++)
            hacc[g * (GS / 2) + u2] = pk2(v[2 * u2], v[2 * u2 + 1]);
    }

    // ---- Linear 2 (packed, 16 outputs per chunk) + max over 16 edges + ReLU ----
    float* outn = out + (long)node * COUT2;
#pragma unroll 1
    for (int c2 = 0; c2 < COUT2; c2 += 16) {
        unsigned long long acc[8];
#pragma unroll
        for (int u = 0; u < 8; u++) acc[u] = pk2(sbb[c2 + 2 * u], sbb[c2 + 2 * u + 1]);

#pragma unroll 2
        for (int p = 0; p < NP; p++) {
            float f0, f1;
            upk2(hacc[p], f0, f1);
            const unsigned long long d0 = pk2(f0, f0);
            const unsigned long long d1 = pk2(f1, f1);
            const ulonglong2* w0 = (const ulonglong2*)(sWb + (2 * p) * COUT2 + c2);
            const ulonglong2* w1 = (const ulonglong2*)(sWb + (2 * p + 1) * COUT2 + c2);
#pragma unroll
            for (int u = 0; u < 4; u++) {
                const ulonglong2 a = w0[u];
                fma2(acc[2 * u + 0], d0, a.x);
                fma2(acc[2 * u + 1], d0, a.y);
            }
#pragma unroll
            for (int u = 0; u < 4; u++) {
                const ulonglong2 a = w1[u];
                fma2(acc[2 * u + 0], d1, a.x);
                fma2(acc[2 * u + 1], d1, a.y);
            }
        }

        float a[16];
#pragma unroll
        for (int u = 0; u < 8; u++) upk2(acc[u], a[2 * u], a[2 * u + 1]);
#pragma unroll
        for (int off = 8; off >= 1; off >>= 1) {
#pragma unroll
            for (int u = 0; u < 16; u++)
                a[u] = fmaxf(a[u], __shfl_xor_sync(0xffffffffu, a[u], off));
        }
        if (e == 0) {
#pragma unroll
            for (int u = 0; u < 16; u++) outn[c2 + u] = fmaxf(a[u], 0.f);
        }
    }
}

// ---------------------------------------------------------------------------
extern "C" void kernel_launch(void* const* d_in, const int* in_sizes, int n_in,
                              void* d_out, int out_size)
{
    const float* pos    = (const float*)d_in[0];
    const float* normal = (const float*)d_in[1];
    const float* W1a = (const float*)d_in[2];
    const float* b1a = (const float*)d_in[3];
    const float* g1  = (const float*)d_in[4];
    const float* be1 = (const float*)d_in[5];
    const float* W1b = (const float*)d_in[6];
    const float* b1b = (const float*)d_in[7];
    const float* W2a = (const float*)d_in[8];
    const float* b2a = (const float*)d_in[9];
    const float* g2  = (const float*)d_in[10];
    const float* be2 = (const float*)d_in[11];
    const float* W2b = (const float*)d_in[12];
    const float* b2b = (const float*)d_in[13];
    const float* W3a = (const float*)d_in[14];
    const float* b3a = (const float*)d_in[15];
    const float* g3  = (const float*)d_in[16];
    const float* be3 = (const float*)d_in[17];
    const float* W3b = (const float*)d_in[18];
    const float* b3b = (const float*)d_in[19];

    float* out = (float*)d_out;
    float* h1 = out;                       // [N,64]
    float* h2 = out + (size_t)N_PTS * 64;  // [N,64]
    float* h3 = out + (size_t)N_PTS * 128; // [N,128]

    void *nbr_p = nullptr, *h0_p = nullptr, *p4_p = nullptr;
    cudaGetSymbolAddress(&nbr_p, g_nbr);
    cudaGetSymbolAddress(&h0_p, g_h0);
    cudaGetSymbolAddress(&p4_p, g_pos4);
    int*    nbr = (int*)nbr_p;
    float*  h0  = (float*)h0_p;
    float4* p4  = (float4*)p4_p;

    const int sm1 = (9 * 64 + 3 * 64 + 64 * 64 + 64) * 4;
    const int sm2 = (67 * 64 + 3 * 64 + 64 * 64 + 64) * 4;
    const int sm3 = (67 * 128 + 3 * 128 + 128 * 128 + 128) * 4;

    cudaFuncSetAttribute(conv_kernel<6, 64, 64, 8>,
                         cudaFuncAttributeMaxDynamicSharedMemorySize, sm1);
    cudaFuncSetAttribute(conv_kernel<64, 64, 64, 8>,
                         cudaFuncAttributeMaxDynamicSharedMemorySize, sm2);
    cudaFuncSetAttribute(conv_kernel<64, 128, 128, 16>,
                         cudaFuncAttributeMaxDynamicSharedMemorySize, sm3);

    prep_kernel<<<N_PTS / 256, 256>>>(pos, p4);
    knn_kernel<<<N_PTS / 64, 64>>>(p4, nbr);
    concat_kernel<<<N_PTS / 256, 256>>>(pos, normal, h0);

    conv_kernel<6, 64, 64, 8><<<N_PTS / 16, 256, sm1>>>(
        h0, pos, nbr, W1a, b1a, g1, be1, W1b, b1b, h1);
    conv_kernel<64, 64, 64, 8><<<N_PTS / 16, 256, sm2>>>(
        h1, pos, nbr, W2a, b2a, g2, be2, W2b, b2b, h2);
    conv_kernel<64, 128, 128, 16><<<N_PTS / 16, 256, sm3>>>(
        h2, pos, nbr, W3a, b3a, g3, be3, W3b, b3b, h3);
}

// round 5
// speedup vs baseline: 3.4598x; 1.3079x over previous
#include <cuda_runtime.h>
#include <cuda_bf16.h>

#define N_PTS 16384
#define KNN   16

__device__ int    g_nbr[N_PTS * KNN];
__device__ float  g_h0[N_PTS * 6];
__device__ float4 g_pos4[N_PTS];

// ---------------- packed f32x2 helpers ----------------
__device__ __forceinline__ unsigned long long pk2(float lo, float hi) {
    unsigned long long r;
    asm("mov.b64 %0, {%1, %2};" : "=l"(r) : "f"(lo), "f"(hi));
    return r;
}
__device__ __forceinline__ void upk2(unsigned long long v, float& lo, float& hi) {
    asm("mov.b64 {%0, %1}, %2;" : "=f"(lo), "=f"(hi) : "l"(v));
}
__device__ __forceinline__ void fma2(unsigned long long& d, unsigned long long a,
                                     unsigned long long b) {
    asm("fma.rn.f32x2 %0, %1, %2, %0;" : "+l"(d) : "l"(a), "l"(b));
}
__device__ __forceinline__ unsigned long long add2(unsigned long long a,
                                                   unsigned long long b) {
    unsigned long long d;
    asm("add.rn.f32x2 %0, %1, %2;" : "=l"(d) : "l"(a), "l"(b));
    return d;
}
__device__ __forceinline__ unsigned long long mul2(unsigned long long a,
                                                   unsigned long long b) {
    unsigned long long d;
    asm("mul.rn.f32x2 %0, %1, %2;" : "=l"(d) : "l"(a), "l"(b));
    return d;
}

// ---------------------------------------------------------------------------
__global__ void prep_kernel(const float* __restrict__ pos, float4* __restrict__ p4)
{
    const int i = blockIdx.x * 256 + threadIdx.x;
    if (i < N_PTS) {
        const float x = pos[3 * i], y = pos[3 * i + 1], z = pos[3 * i + 2];
        p4[i] = make_float4(x, y, z, fmaf(x, x, fmaf(y, y, z * z)));
    }
}

// ---------------------------------------------------------------------------
// kNN: branch-free register insertion network (unchanged from R4).
// ---------------------------------------------------------------------------
__global__ void __launch_bounds__(64) knn_kernel(const float4* __restrict__ p4,
                                                 int* __restrict__ nbr)
{
    const int tid = threadIdx.x;
    const int q   = blockIdx.x * 64 + tid;
    const float4 me = p4[q];
    const float px = me.x, py = me.y, pz = me.z, sq = me.w;

    __shared__ float4 tile[256];

    float bestd[KNN];
    int   besti[KNN];
#pragma unroll
    for (int r = 0; r < KNN; r++) { bestd[r] = 3.4e38f; besti[r] = 0; }
    float thr = 3.4e38f;

    for (int t0 = 0; t0 < N_PTS; t0 += 256) {
        __syncthreads();
#pragma unroll
        for (int u = 0; u < 4; u++) tile[tid + 64 * u] = p4[t0 + tid + 64 * u];
        __syncthreads();
#pragma unroll 4
        for (int jj = 0; jj < 256; jj++) {
            const float4 c = tile[jj];
            const float dot = fmaf(px, c.x, fmaf(py, c.y, pz * c.z));
            const float d2  = fmaf(-2.0f, dot, sq + c.w);
            if (d2 < thr) {
                const int idx = t0 + jj;
#pragma unroll
                for (int r = KNN - 1; r >= 1; r--) {
                    const bool keep  = bestd[r] <= d2;
                    const bool shift = bestd[r - 1] > d2;
                    bestd[r] = keep ? bestd[r] : (shift ? bestd[r - 1] : d2);
                    besti[r] = keep ? besti[r] : (shift ? besti[r - 1] : idx);
                }
                {
                    const bool keep = bestd[0] <= d2;
                    bestd[0] = keep ? bestd[0] : d2;
                    besti[0] = keep ? besti[0] : idx;
                }
                thr = bestd[KNN - 1];
            }
        }
    }
#pragma unroll
    for (int r = 0; r < KNN; r++) nbr[q * KNN + r] = besti[r];
}

// ---------------------------------------------------------------------------
__global__ void concat_kernel(const float* __restrict__ pos,
                              const float* __restrict__ normal,
                              float* __restrict__ h0)
{
    const int i = blockIdx.x * 256 + threadIdx.x;
    if (i < N_PTS) {
#pragma unroll
        for (int c = 0; c < 3; c++) {
            h0[i * 6 + c]     = pos[i * 3 + c];
            h0[i * 6 + 3 + c] = normal[i * 3 + c];
        }
    }
}

// ---------------------------------------------------------------------------
// SMEM-tiled fused PointNetConv.
// Block = 256 threads, 16 nodes = 256 edges (E).
// Phase 0: gather m[CIN][E] into SMEM (edge-minor), load weights.
// Phase 1: GEMM1, per-thread tile 8 edges x NC channels (packed over edges).
// Phase 2: GroupNorm+ReLU (thread-local; channel tile aligned to groups of 8),
//          write h[C1][E] to SMEM.
// Phase 3: GEMM2, same tiling; per-node max over 16 edges, ReLU, store.
// ---------------------------------------------------------------------------
template <int CIN_X, int C1, int C2>
__global__ void __launch_bounds__(256) conv_kernel(
    const float* __restrict__ x, const float* __restrict__ pos,
    const int* __restrict__ nbr,
    const float* __restrict__ Wa, const float* __restrict__ ba,
    const float* __restrict__ gmm, const float* __restrict__ bet,
    const float* __restrict__ Wb, const float* __restrict__ bb,
    float* __restrict__ out)
{
    constexpr int CIN = CIN_X + 3;
    constexpr int E   = 256;
    constexpr int EP  = 260;              // padded edge stride (16B-aligned rows)
    constexpr int NC  = C1 / 8;           // channels per thread (8 or 16)
    constexpr int NG  = NC / 8;           // groups per thread (group size 8)
    constexpr int R0F = (CIN * EP + CIN * C1 > C1 * EP) ? (CIN * EP + CIN * C1)
                                                        : (C1 * EP);

    extern __shared__ float smf[];
    float* sM  = smf;                 // CIN*EP   (phase 0/1)
    float* sWa = smf + CIN * EP;      // CIN*C1   (phase 0/1)
    float* sH  = smf;                 // C1*EP    (phase 2/3, overlaps sM/sWa)
    float* sWb = smf + R0F;           // C1*C2
    float* sba = sWb + C1 * C2;
    float* sg  = sba + C1;
    float* sbe = sg + C1;
    float* sbb = sbe + C1;            // C2

    const int tid = threadIdx.x;
    const int eo  = tid >> 3;         // edge octet 0..31
    const int co  = tid & 7;          // channel octet 0..7

    // ---- phase 0: weights + biases + gather ----
    for (int i = tid; i < CIN * C1; i += 256) sWa[i] = Wa[i];
    for (int i = tid; i < C1 * C2; i += 256) sWb[i] = Wb[i];
    if (tid < C1) { sba[tid] = ba[tid]; sg[tid] = gmm[tid]; sbe[tid] = bet[tid]; }
    if (tid < C2) sbb[tid] = bb[tid];

    {
        const int e    = tid;
        const int node = (blockIdx.x << 4) + (e >> 4);
        const int j    = nbr[(node << 4) + (e & 15)];
        if constexpr (CIN_X == 6) {
            const float2* xj2 = (const float2*)(x + (long)j * 6);
#pragma unroll
            for (int p = 0; p < 3; p++) {
                const float2 v = __ldg(xj2 + p);
                sM[(2 * p) * EP + e]     = v.x;
                sM[(2 * p + 1) * EP + e] = v.y;
            }
        } else {
            const float4* xj4 = (const float4*)(x + (long)j * CIN_X);
#pragma unroll
            for (int p = 0; p < CIN_X / 4; p++) {
                const float4 v = __ldg(xj4 + p);
                sM[(4 * p) * EP + e]     = v.x;
                sM[(4 * p + 1) * EP + e] = v.y;
                sM[(4 * p + 2) * EP + e] = v.z;
                sM[(4 * p + 3) * EP + e] = v.w;
            }
        }
        sM[(CIN_X + 0) * EP + e] = pos[3 * j]     - pos[3 * node];
        sM[(CIN_X + 1) * EP + e] = pos[3 * j + 1] - pos[3 * node + 1];
        sM[(CIN_X + 2) * EP + e] = pos[3 * j + 2] - pos[3 * node + 2];
    }
    __syncthreads();

    // ---- phase 1: GEMM1  acc[c][ep] over 8 edges x NC channels ----
    unsigned long long acc[NC][4];
#pragma unroll
    for (int c = 0; c < NC; c++) {
        const float b = sba[co * NC + c];
        const unsigned long long bd = pk2(b, b);
#pragma unroll
        for (int ep = 0; ep < 4; ep++) acc[c][ep] = bd;
    }
#pragma unroll 2
    for (int k = 0; k < CIN; k++) {
        const ulonglong2 mv0 = *(const ulonglong2*)(sM + k * EP + 8 * eo);
        const ulonglong2 mv1 = *(const ulonglong2*)(sM + k * EP + 8 * eo + 4);
        float wv[NC];
#pragma unroll
        for (int q4 = 0; q4 < NC / 4; q4++) {
            const float4 t = *(const float4*)(sWa + k * C1 + co * NC + 4 * q4);
            wv[4 * q4] = t.x; wv[4 * q4 + 1] = t.y;
            wv[4 * q4 + 2] = t.z; wv[4 * q4 + 3] = t.w;
        }
#pragma unroll
        for (int c = 0; c < NC; c++) {
            const unsigned long long wd = pk2(wv[c], wv[c]);
            fma2(acc[c][0], mv0.x, wd);
            fma2(acc[c][1], mv0.y, wd);
            fma2(acc[c][2], mv1.x, wd);
            fma2(acc[c][3], mv1.y, wd);
        }
    }
    __syncthreads();   // done reading sM/sWa; sH may overwrite them

    // ---- phase 2: GroupNorm + ReLU + store h to SMEM ----
#pragma unroll
    for (int gi = 0; gi < NG; gi++) {
        const int cb = gi * 8;                       // local channel base
#pragma unroll
        for (int ep = 0; ep < 4; ep++) {
            unsigned long long s = acc[cb][ep];
            unsigned long long qq = mul2(acc[cb][ep], acc[cb][ep]);
#pragma unroll
            for (int c = 1; c < 8; c++) {
                s = add2(s, acc[cb + c][ep]);
                fma2(qq, acc[cb + c][ep], acc[cb + c][ep]);
            }
            float s0, s1, q0, q1;
            upk2(s, s0, s1);
            upk2(qq, q0, q1);
            const float mu0 = s0 * 0.125f, mu1 = s1 * 0.125f;
            const float rs0 = rsqrtf(fmaf(-mu0, mu0, q0 * 0.125f) + 1e-5f);
            const float rs1 = rsqrtf(fmaf(-mu1, mu1, q1 * 0.125f) + 1e-5f);
#pragma unroll
            for (int c = 0; c < 8; c++) {
                const int gc = co * NC + cb + c;
                const float gam = sg[gc], bet_ = sbe[gc];
                float v0, v1;
                upk2(acc[cb + c][ep], v0, v1);
                v0 = fmaxf(fmaf((v0 - mu0) * rs0, gam, bet_), 0.f);
                v1 = fmaxf(fmaf((v1 - mu1) * rs1, gam, bet_), 0.f);
                *(float2*)(sH + gc * EP + 8 * eo + 2 * ep) = make_float2(v0, v1);
            }
        }
    }
    __syncthreads();

    // ---- phase 3: GEMM2 ----
    unsigned long long a2[NC][4];
#pragma unroll
    for (int c = 0; c < NC; c++) {
        const float b = sbb[co * NC + c];
        const unsigned long long bd = pk2(b, b);
#pragma unroll
        for (int ep = 0; ep < 4; ep++) a2[c][ep] = bd;
    }
#pragma unroll 2
    for (int k = 0; k < C1; k++) {
        const ulonglong2 hv0 = *(const ulonglong2*)(sH + k * EP + 8 * eo);
        const ulonglong2 hv1 = *(const ulonglong2*)(sH + k * EP + 8 * eo + 4);
        float wv[NC];
#pragma unroll
        for (int q4 = 0; q4 < NC / 4; q4++) {
            const float4 t = *(const float4*)(sWb + k * C2 + co * NC + 4 * q4);
            wv[4 * q4] = t.x; wv[4 * q4 + 1] = t.y;
            wv[4 * q4 + 2] = t.z; wv[4 * q4 + 3] = t.w;
        }
#pragma unroll
        for (int c = 0; c < NC; c++) {
            const unsigned long long wd = pk2(wv[c], wv[c]);
            fma2(a2[c][0], hv0.x, wd);
            fma2(a2[c][1], hv0.y, wd);
            fma2(a2[c][2], hv1.x, wd);
            fma2(a2[c][3], hv1.y, wd);
        }
    }

    // ---- per-node max over 16 edges + ReLU + store ----
    float vmax[NC];
#pragma unroll
    for (int c = 0; c < NC; c++) {
        float m0, m1, t0, t1;
        upk2(a2[c][0], m0, m1);
        m0 = fmaxf(m0, m1);
        upk2(a2[c][1], t0, t1);
        m0 = fmaxf(m0, fmaxf(t0, t1));
        upk2(a2[c][2], t0, t1);
        m0 = fmaxf(m0, fmaxf(t0, t1));
        upk2(a2[c][3], t0, t1);
        m0 = fmaxf(m0, fmaxf(t0, t1));
        vmax[c] = m0;
    }
#pragma unroll
    for (int c = 0; c < NC; c++)
        vmax[c] = fmaxf(vmax[c], __shfl_xor_sync(0xffffffffu, vmax[c], 8));

    if (!(eo & 1)) {
        const int node = (blockIdx.x << 4) + (eo >> 1);
        float* op = out + (long)node * C2 + co * NC;
#pragma unroll
        for (int q4 = 0; q4 < NC / 4; q4++) {
            *(float4*)(op + 4 * q4) = make_float4(
                fmaxf(vmax[4 * q4], 0.f),     fmaxf(vmax[4 * q4 + 1], 0.f),
                fmaxf(vmax[4 * q4 + 2], 0.f), fmaxf(vmax[4 * q4 + 3], 0.f));
        }
    }
}

// ---------------------------------------------------------------------------
template <int CIN_X, int C1, int C2>
static int conv_smem_bytes()
{
    constexpr int CIN = CIN_X + 3;
    constexpr int EP  = 260;
    constexpr int R0F = (CIN * EP + CIN * C1 > C1 * EP) ? (CIN * EP + CIN * C1)
                                                        : (C1 * EP);
    return (R0F + C1 * C2 + 3 * C1 + C2) * 4;
}

extern "C" void kernel_launch(void* const* d_in, const int* in_sizes, int n_in,
                              void* d_out, int out_size)
{
    const float* pos    = (const float*)d_in[0];
    const float* normal = (const float*)d_in[1];
    const float* W1a = (const float*)d_in[2];
    const float* b1a = (const float*)d_in[3];
    const float* g1  = (const float*)d_in[4];
    const float* be1 = (const float*)d_in[5];
    const float* W1b = (const float*)d_in[6];
    const float* b1b = (const float*)d_in[7];
    const float* W2a = (const float*)d_in[8];
    const float* b2a = (const float*)d_in[9];
    const float* g2  = (const float*)d_in[10];
    const float* be2 = (const float*)d_in[11];
    const float* W2b = (const float*)d_in[12];
    const float* b2b = (const float*)d_in[13];
    const float* W3a = (const float*)d_in[14];
    const float* b3a = (const float*)d_in[15];
    const float* g3  = (const float*)d_in[16];
    const float* be3 = (const float*)d_in[17];
    const float* W3b = (const float*)d_in[18];
    const float* b3b = (const float*)d_in[19];

    float* out = (float*)d_out;
    float* h1 = out;
    float* h2 = out + (size_t)N_PTS * 64;
    float* h3 = out + (size_t)N_PTS * 128;

    void *nbr_p = nullptr, *h0_p = nullptr, *p4_p = nullptr;
    cudaGetSymbolAddress(&nbr_p, g_nbr);
    cudaGetSymbolAddress(&h0_p, g_h0);
    cudaGetSymbolAddress(&p4_p, g_pos4);
    int*    nbr = (int*)nbr_p;
    float*  h0  = (float*)h0_p;
    float4* p4  = (float4*)p4_p;

    const int sm1 = conv_smem_bytes<6, 64, 64>();
    const int sm2 = conv_smem_bytes<64, 64, 64>();
    const int sm3 = conv_smem_bytes<64, 128, 128>();

    cudaFuncSetAttribute(conv_kernel<6, 64, 64>,
                         cudaFuncAttributeMaxDynamicSharedMemorySize, sm1);
    cudaFuncSetAttribute(conv_kernel<64, 64, 64>,
                         cudaFuncAttributeMaxDynamicSharedMemorySize, sm2);
    cudaFuncSetAttribute(conv_kernel<64, 128, 128>,
                         cudaFuncAttributeMaxDynamicSharedMemorySize, sm3);

    prep_kernel<<<N_PTS / 256, 256>>>(pos, p4);
    knn_kernel<<<N_PTS / 64, 64>>>(p4, nbr);
    concat_kernel<<<N_PTS / 256, 256>>>(pos, normal, h0);

    conv_kernel<6, 64, 64><<<N_PTS / 16, 256, sm1>>>(
        h0, pos, nbr, W1a, b1a, g1, be1, W1b, b1b, h1);
    conv_kernel<64, 64, 64><<<N_PTS / 16, 256, sm2>>>(
        h1, pos, nbr, W2a, b2a, g2, be2, W2b, b2b, h2);
    conv_kernel<64, 128, 128><<<N_PTS / 16, 256, sm3>>>(
        h2, pos, nbr, W3a, b3a, g3, be3, W3b, b3b, h3);
}

// round 8
// speedup vs baseline: 3.8793x; 1.1212x over previous
#include <cuda_runtime.h>
#include <cuda_bf16.h>

#define N_PTS 16384
#define KNN   16

__device__ int    g_nbr[N_PTS * KNN];
__device__ float  g_h0[N_PTS * 6];
__device__ float4 g_pos4[N_PTS];

// ---------------- packed f32x2 helpers ----------------
__device__ __forceinline__ unsigned long long pk2(float lo, float hi) {
    unsigned long long r;
    asm("mov.b64 %0, {%1, %2};" : "=l"(r) : "f"(lo), "f"(hi));
    return r;
}
__device__ __forceinline__ void upk2(unsigned long long v, float& lo, float& hi) {
    asm("mov.b64 {%0, %1}, %2;" : "=f"(lo), "=f"(hi) : "l"(v));
}
__device__ __forceinline__ void fma2(unsigned long long& d, unsigned long long a,
                                     unsigned long long b) {
    asm("fma.rn.f32x2 %0, %1, %2, %0;" : "+l"(d) : "l"(a), "l"(b));
}
__device__ __forceinline__ unsigned long long add2(unsigned long long a,
                                                   unsigned long long b) {
    unsigned long long d;
    asm("add.rn.f32x2 %0, %1, %2;" : "=l"(d) : "l"(a), "l"(b));
    return d;
}
__device__ __forceinline__ unsigned long long mul2(unsigned long long a,
                                                   unsigned long long b) {
    unsigned long long d;
    asm("mul.rn.f32x2 %0, %1, %2;" : "=l"(d) : "l"(a), "l"(b));
    return d;
}

// ---------------------------------------------------------------------------
__global__ void prep_kernel(const float* __restrict__ pos, float4* __restrict__ p4)
{
    const int i = blockIdx.x * 256 + threadIdx.x;
    if (i < N_PTS) {
        const float x = pos[3 * i], y = pos[3 * i + 1], z = pos[3 * i + 2];
        p4[i] = make_float4(x, y, z, fmaf(x, x, fmaf(y, y, z * z)));
    }
}

// ---------------------------------------------------------------------------
// kNN: 4 lanes per query (split candidate range in quarters). Each lane keeps
// a local top-16 via a branch-free register insertion network; the 4 sibling
// lanes share a pruning threshold (min of local 16th-best — a safe upper bound
// on the final global 16th-best). Final 4-way merge on u64 keys (sortable
// float bits | idx) selects the exact global top-16 set with stable ties.
// ---------------------------------------------------------------------------
__global__ void __launch_bounds__(256) knn_kernel(const float4* __restrict__ p4,
                                                  int* __restrict__ nbr)
{
    __shared__ unsigned long long sbuf[4096];          // 32KB, dual-purpose
    float4* tiles = reinterpret_cast<float4*>(sbuf);   // 4 tiles, stride 258

    const int tid = threadIdx.x;
    const int s   = tid & 3;          // split 0..3
    const int ql  = tid >> 2;         // query-local 0..63
    const int q   = blockIdx.x * 64 + ql;
    const float4 me = p4[q];
    const float px = me.x, py = me.y, pz = me.z, sq = me.w;

    float bestd[KNN];
    int   besti[KNN];
#pragma unroll
    for (int r = 0; r < KNN; r++) { bestd[r] = 3.4e38f; besti[r] = 0; }
    float thr_g = 3.4e38f;

    const int cbase = s * 4096;
    for (int it = 0; it < 16; it++) {
        __syncthreads();
#pragma unroll
        for (int u = 0; u < 4; u++)
            tiles[u * 258 + tid] = p4[u * 4096 + it * 256 + tid];
        __syncthreads();

        const float4* mytile = tiles + s * 258;
        const int ibase = cbase + it * 256;
#pragma unroll 4
        for (int jj = 0; jj < 256; jj++) {
            const float4 c = mytile[jj];
            const float dot = fmaf(px, c.x, fmaf(py, c.y, pz * c.z));
            const float d2  = fmaf(-2.0f, dot, sq + c.w);
            if (d2 <= thr_g) {
                const int idx = ibase + jj;
#pragma unroll
                for (int r = KNN - 1; r >= 1; r--) {
                    const bool keep  = bestd[r] <= d2;       // stable ties
                    const bool shift = bestd[r - 1] > d2;    // strict
                    bestd[r] = keep ? bestd[r] : (shift ? bestd[r - 1] : d2);
                    besti[r] = keep ? besti[r] : (shift ? besti[r - 1] : idx);
                }
                {
                    const bool keep = bestd[0] <= d2;
                    bestd[0] = keep ? bestd[0] : d2;
                    besti[0] = keep ? besti[0] : idx;
                }
                thr_g = fminf(thr_g, bestd[KNN - 1]);
            }
        }
        // share pruning threshold across the 4 sibling lanes
        float t = bestd[KNN - 1];
        t = fminf(t, __shfl_xor_sync(0xffffffffu, t, 1));
        t = fminf(t, __shfl_xor_sync(0xffffffffu, t, 2));
        thr_g = t;
    }

    // ---- merge the 4 sorted local lists into the global top-16 set ----
    __syncthreads();   // done with tiles; reuse sbuf as merge lists
    unsigned long long* mylist = sbuf + (ql * 4 + s) * 16;
#pragma unroll
    for (int r = 0; r < KNN; r++) {
        unsigned int db = __float_as_uint(bestd[r]);
        db ^= (db & 0x80000000u) ? 0xFFFFFFFFu : 0x80000000u;  // sortable bits
        mylist[r] = ((unsigned long long)db << 32) | (unsigned int)besti[r];
    }
    __syncwarp();

    int p = 0;
#pragma unroll 1
    for (int r = 0; r < KNN; r++) {
        unsigned long long k = (p < KNN) ? mylist[p] : ~0ull;
        unsigned long long o = __shfl_xor_sync(0xffffffffu, k, 1);
        unsigned long long km = (k < o) ? k : o;
        o = __shfl_xor_sync(0xffffffffu, km, 2);
        km = (km < o) ? km : o;
        if (k == km) {                     // unique winner (idx in key)
            nbr[q * KNN + r] = (int)(unsigned int)(km & 0xffffffffu);
            p++;
        }
    }
}

// ---------------------------------------------------------------------------
__global__ void concat_kernel(const float* __restrict__ pos,
                              const float* __restrict__ normal,
                              float* __restrict__ h0)
{
    const int i = blockIdx.x * 256 + threadIdx.x;
    if (i < N_PTS) {
#pragma unroll
        for (int c = 0; c < 3; c++) {
            h0[i * 6 + c]     = pos[i * 3 + c];
            h0[i * 6 + 3 + c] = normal[i * 3 + c];
        }
    }
}

// ---------------------------------------------------------------------------
// SMEM-tiled fused PointNetConv (unchanged from R5).
// ---------------------------------------------------------------------------
template <int CIN_X, int C1, int C2>
__global__ void __launch_bounds__(256) conv_kernel(
    const float* __restrict__ x, const float* __restrict__ pos,
    const int* __restrict__ nbr,
    const float* __restrict__ Wa, const float* __restrict__ ba,
    const float* __restrict__ gmm, const float* __restrict__ bet,
    const float* __restrict__ Wb, const float* __restrict__ bb,
    float* __restrict__ out)
{
    constexpr int CIN = CIN_X + 3;
    constexpr int EP  = 260;
    constexpr int NC  = C1 / 8;
    constexpr int NG  = NC / 8;
    constexpr int R0F = (CIN * EP + CIN * C1 > C1 * EP) ? (CIN * EP + CIN * C1)
                                                        : (C1 * EP);

    extern __shared__ float smf[];
    float* sM  = smf;
    float* sWa = smf + CIN * EP;
    float* sH  = smf;
    float* sWb = smf + R0F;
    float* sba = sWb + C1 * C2;
    float* sg  = sba + C1;
    float* sbe = sg + C1;
    float* sbb = sbe + C1;

    const int tid = threadIdx.x;
    const int eo  = tid >> 3;
    const int co  = tid & 7;

    for (int i = tid; i < CIN * C1; i += 256) sWa[i] = Wa[i];
    for (int i = tid; i < C1 * C2; i += 256) sWb[i] = Wb[i];
    if (tid < C1) { sba[tid] = ba[tid]; sg[tid] = gmm[tid]; sbe[tid] = bet[tid]; }
    if (tid < C2) sbb[tid] = bb[tid];

    {
        const int e    = tid;
        const int node = (blockIdx.x << 4) + (e >> 4);
        const int j    = nbr[(node << 4) + (e & 15)];
        if constexpr (CIN_X == 6) {
            const float2* xj2 = (const float2*)(x + (long)j * 6);
#pragma unroll
            for (int p = 0; p < 3; p++) {
                const float2 v = __ldg(xj2 + p);
                sM[(2 * p) * EP + e]     = v.x;
                sM[(2 * p + 1) * EP + e] = v.y;
            }
        } else {
            const float4* xj4 = (const float4*)(x + (long)j * CIN_X);
#pragma unroll
            for (int p = 0; p < CIN_X / 4; p++) {
                const float4 v = __ldg(xj4 + p);
                sM[(4 * p) * EP + e]     = v.x;
                sM[(4 * p + 1) * EP + e] = v.y;
                sM[(4 * p + 2) * EP + e] = v.z;
                sM[(4 * p + 3) * EP + e] = v.w;
            }
        }
        sM[(CIN_X + 0) * EP + e] = pos[3 * j]     - pos[3 * node];
        sM[(CIN_X + 1) * EP + e] = pos[3 * j + 1] - pos[3 * node + 1];
        sM[(CIN_X + 2) * EP + e] = pos[3 * j + 2] - pos[3 * node + 2];
    }
    __syncthreads();

    unsigned long long acc[NC][4];
#pragma unroll
    for (int c = 0; c < NC; c++) {
        const float b = sba[co * NC + c];
        const unsigned long long bd = pk2(b, b);
#pragma unroll
        for (int ep = 0; ep < 4; ep++) acc[c][ep] = bd;
    }
#pragma unroll 2
    for (int k = 0; k < CIN; k++) {
        const ulonglong2 mv0 = *(const ulonglong2*)(sM + k * EP + 8 * eo);
        const ulonglong2 mv1 = *(const ulonglong2*)(sM + k * EP + 8 * eo + 4);
        float wv[NC];
#pragma unroll
        for (int q4 = 0; q4 < NC / 4; q4++) {
            const float4 t = *(const float4*)(sWa + k * C1 + co * NC + 4 * q4);
            wv[4 * q4] = t.x; wv[4 * q4 + 1] = t.y;
            wv[4 * q4 + 2] = t.z; wv[4 * q4 + 3] = t.w;
        }
#pragma unroll
        for (int c = 0; c < NC; c++) {
            const unsigned long long wd = pk2(wv[c], wv[c]);
            fma2(acc[c][0], mv0.x, wd);
            fma2(acc[c][1], mv0.y, wd);
            fma2(acc[c][2], mv1.x, wd);
            fma2(acc[c][3], mv1.y, wd);
        }
    }
    __syncthreads();

#pragma unroll
    for (int gi = 0; gi < NG; gi++) {
        const int cb = gi * 8;
#pragma unroll
        for (int ep = 0; ep < 4; ep++) {
            unsigned long long ssum = acc[cb][ep];
            unsigned long long qq = mul2(acc[cb][ep], acc[cb][ep]);
#pragma unroll
            for (int c = 1; c < 8; c++) {
                ssum = add2(ssum, acc[cb + c][ep]);
                fma2(qq, acc[cb + c][ep], acc[cb + c][ep]);
            }
            float s0, s1, q0, q1;
            upk2(ssum, s0, s1);
            upk2(qq, q0, q1);
            const float mu0 = s0 * 0.125f, mu1 = s1 * 0.125f;
            const float rs0 = rsqrtf(fmaf(-mu0, mu0, q0 * 0.125f) + 1e-5f);
            const float rs1 = rsqrtf(fmaf(-mu1, mu1, q1 * 0.125f) + 1e-5f);
#pragma unroll
            for (int c = 0; c < 8; c++) {
                const int gc = co * NC + cb + c;
                const float gam = sg[gc], bet_ = sbe[gc];
                float v0, v1;
                upk2(acc[cb + c][ep], v0, v1);
                v0 = fmaxf(fmaf((v0 - mu0) * rs0, gam, bet_), 0.f);
                v1 = fmaxf(fmaf((v1 - mu1) * rs1, gam, bet_), 0.f);
                *(float2*)(sH + gc * EP + 8 * eo + 2 * ep) = make_float2(v0, v1);
            }
        }
    }
    __syncthreads();

    unsigned long long a2[NC][4];
#pragma unroll
    for (int c = 0; c < NC; c++) {
        const float b = sbb[co * NC + c];
        const unsigned long long bd = pk2(b, b);
#pragma unroll
        for (int ep = 0; ep < 4; ep++) a2[c][ep] = bd;
    }
#pragma unroll 2
    for (int k = 0; k < C1; k++) {
        const ulonglong2 hv0 = *(const ulonglong2*)(sH + k * EP + 8 * eo);
        const ulonglong2 hv1 = *(const ulonglong2*)(sH + k * EP + 8 * eo + 4);
        float wv[NC];
#pragma unroll
        for (int q4 = 0; q4 < NC / 4; q4++) {
            const float4 t = *(const float4*)(sWb + k * C2 + co * NC + 4 * q4);
            wv[4 * q4] = t.x; wv[4 * q4 + 1] = t.y;
            wv[4 * q4 + 2] = t.z; wv[4 * q4 + 3] = t.w;
        }
#pragma unroll
        for (int c = 0; c < NC; c++) {
            const unsigned long long wd = pk2(wv[c], wv[c]);
            fma2(a2[c][0], hv0.x, wd);
            fma2(a2[c][1], hv0.y, wd);
            fma2(a2[c][2], hv1.x, wd);
            fma2(a2[c][3], hv1.y, wd);
        }
    }

    float vmax[NC];
#pragma unroll
    for (int c = 0; c < NC; c++) {
        float m0, m1, t0, t1;
        upk2(a2[c][0], m0, m1);
        m0 = fmaxf(m0, m1);
        upk2(a2[c][1], t0, t1);
        m0 = fmaxf(m0, fmaxf(t0, t1));
        upk2(a2[c][2], t0, t1);
        m0 = fmaxf(m0, fmaxf(t0, t1));
        upk2(a2[c][3], t0, t1);
        m0 = fmaxf(m0, fmaxf(t0, t1));
        vmax[c] = m0;
    }
#pragma unroll
    for (int c = 0; c < NC; c++)
        vmax[c] = fmaxf(vmax[c], __shfl_xor_sync(0xffffffffu, vmax[c], 8));

    if (!(eo & 1)) {
        const int node = (blockIdx.x << 4) + (eo >> 1);
        float* op = out + (long)node * C2 + co * NC;
#pragma unroll
        for (int q4 = 0; q4 < NC / 4; q4++) {
            *(float4*)(op + 4 * q4) = make_float4(
                fmaxf(vmax[4 * q4], 0.f),     fmaxf(vmax[4 * q4 + 1], 0.f),
                fmaxf(vmax[4 * q4 + 2], 0.f), fmaxf(vmax[4 * q4 + 3], 0.f));
        }
    }
}

// ---------------------------------------------------------------------------
template <int CIN_X, int C1, int C2>
static int conv_smem_bytes()
{
    constexpr int CIN = CIN_X + 3;
    constexpr int EP  = 260;
    constexpr int R0F = (CIN * EP + CIN * C1 > C1 * EP) ? (CIN * EP + CIN * C1)
                                                        : (C1 * EP);
    return (R0F + C1 * C2 + 3 * C1 + C2) * 4;
}

extern "C" void kernel_launch(void* const* d_in, const int* in_sizes, int n_in,
                              void* d_out, int out_size)
{
    const float* pos    = (const float*)d_in[0];
    const float* normal = (const float*)d_in[1];
    const float* W1a = (const float*)d_in[2];
    const float* b1a = (const float*)d_in[3];
    const float* g1  = (const float*)d_in[4];
    const float* be1 = (const float*)d_in[5];
    const float* W1b = (const float*)d_in[6];
    const float* b1b = (const float*)d_in[7];
    const float* W2a = (const float*)d_in[8];
    const float* b2a = (const float*)d_in[9];
    const float* g2  = (const float*)d_in[10];
    const float* be2 = (const float*)d_in[11];
    const float* W2b = (const float*)d_in[12];
    const float* b2b = (const float*)d_in[13];
    const float* W3a = (const float*)d_in[14];
    const float* b3a = (const float*)d_in[15];
    const float* g3  = (const float*)d_in[16];
    const float* be3 = (const float*)d_in[17];
    const float* W3b = (const float*)d_in[18];
    const float* b3b = (const float*)d_in[19];

    float* out = (float*)d_out;
    float* h1 = out;
    float* h2 = out + (size_t)N_PTS * 64;
    float* h3 = out + (size_t)N_PTS * 128;

    void *nbr_p = nullptr, *h0_p = nullptr, *p4_p = nullptr;
    cudaGetSymbolAddress(&nbr_p, g_nbr);
    cudaGetSymbolAddress(&h0_p, g_h0);
    cudaGetSymbolAddress(&p4_p, g_pos4);
    int*    nbr = (int*)nbr_p;
    float*  h0  = (float*)h0_p;
    float4* p4  = (float4*)p4_p;

    const int sm1 = conv_smem_bytes<6, 64, 64>();
    const int sm2 = conv_smem_bytes<64, 64, 64>();
    const int sm3 = conv_smem_bytes<64, 128, 128>();

    cudaFuncSetAttribute(conv_kernel<6, 64, 64>,
                         cudaFuncAttributeMaxDynamicSharedMemorySize, sm1);
    cudaFuncSetAttribute(conv_kernel<64, 64, 64>,
                         cudaFuncAttributeMaxDynamicSharedMemorySize, sm2);
    cudaFuncSetAttribute(conv_kernel<64, 128, 128>,
                         cudaFuncAttributeMaxDynamicSharedMemorySize, sm3);

    prep_kernel<<<N_PTS / 256, 256>>>(pos, p4);
    knn_kernel<<<N_PTS / 64, 256>>>(p4, nbr);
    concat_kernel<<<N_PTS / 256, 256>>>(pos, normal, h0);

    conv_kernel<6, 64, 64><<<N_PTS / 16, 256, sm1>>>(
        h0, pos, nbr, W1a, b1a, g1, be1, W1b, b1b, h1);
    conv_kernel<64, 64, 64><<<N_PTS / 16, 256, sm2>>>(
        h1, pos, nbr, W2a, b2a, g2, be2, W2b, b2b, h2);
    conv_kernel<64, 128, 128><<<N_PTS / 16, 256, sm3>>>(
        h2, pos, nbr, W3a, b3a, g3, be3, W3b, b3b, h3);
}